// round 11
// baseline (speedup 1.0000x reference)
#include <cuda_runtime.h>
#include <cuda_bf16.h>
#include <cstdint>

// ===========================================================================
// GRU cell via mma.sync (sm_103 non-'a' target: tcgen05 unavailable).
// 3-term bf16 split: C = Ah*Bh + Al*Bh + Ah*Bl  (~2^-17 effective precision).
// R11: (a) per-warp k-step rotation to de-phase the 4 warps of each SMSP
// (post-barrier LDG/LDSM heads were correlated -> tensor gaps), (b) 3-stage
// A pipeline with cp_wait<1> for a full stage of copy slack.
//   CTA tile M=128 x N=64, 512 threads = 16 warps (2m x 8n), warp m64 x n8.
//   B operands direct from L2 via LDG.64, double-buffered in registers.
// ===========================================================================

#define NT_COUNT 8           // 512 / 64
#define MT_COUNT 128         // 16384 / 128
#define NSTAGE 3

// packed A: [mt 128][chunk 32][plane 2][row 128][64B]  = 64 MB
__device__ __align__(128) unsigned char g_Apack[128u * 32u * 2u * 128u * 64u];
// packed W: [nt 8][gate 3][chunk 32][plane 2][k16half 2][n 64][32B] = 6 MB
//   32B per (n, k16): pairs stored as (q, q+4) adjacent -> one LDG.64 = {b0,b1}
__device__ __align__(128) unsigned char g_Wpack[8u * 3u * 32u * 2u * 2u * 64u * 32u];

// smem: A only. 144B row stride (36 banks -> conflict-free ldmatrix):
//   plane p: p*18432 + r*144   (128 rows, 128B data = k64)
#define ROWB 144
#define PLSTR 18432
#define STAGE_BYTES 36864
#define SMEM_TOTAL (NSTAGE * STAGE_BYTES)   // 110592

__device__ __forceinline__ uint32_t smem_u32(const void* p) {
    uint32_t a;
    asm("{ .reg .u64 t; cvta.to.shared.u64 t, %1; cvt.u32.u64 %0, t; }"
        : "=r"(a) : "l"(p));
    return a;
}

__device__ __forceinline__ void cp16(uint32_t dst, const void* src) {
    asm volatile("cp.async.cg.shared.global [%0], [%1], 16;"
                 :: "r"(dst), "l"(src) : "memory");
}
__device__ __forceinline__ void cp_commit() {
    asm volatile("cp.async.commit_group;" ::: "memory");
}
template <int N> __device__ __forceinline__ void cp_wait() {
    asm volatile("cp.async.wait_group %0;" :: "n"(N) : "memory");
}

__device__ __forceinline__ void ldm4(uint32_t r[4], uint32_t addr) {
    asm volatile("ldmatrix.sync.aligned.m8n8.x4.shared.b16 {%0,%1,%2,%3}, [%4];"
                 : "=r"(r[0]), "=r"(r[1]), "=r"(r[2]), "=r"(r[3]) : "r"(addr));
}

__device__ __forceinline__ void mma16(float c[4], const uint32_t a[4],
                                      uint32_t b0, uint32_t b1) {
    asm volatile(
        "mma.sync.aligned.m16n8k16.row.col.f32.bf16.bf16.f32 "
        "{%0,%1,%2,%3}, {%4,%5,%6,%7}, {%8,%9}, {%0,%1,%2,%3};\n"
        : "+f"(c[0]), "+f"(c[1]), "+f"(c[2]), "+f"(c[3])
        : "r"(a[0]), "r"(a[1]), "r"(a[2]), "r"(a[3]), "r"(b0), "r"(b1));
}

__device__ __forceinline__ uint32_t pack_hi(float a, float b, uint32_t& lo) {
    __nv_bfloat16 ha = __float2bfloat16(a);
    __nv_bfloat16 hb = __float2bfloat16(b);
    float ra = a - __bfloat162float(ha);
    float rb = b - __bfloat162float(hb);
    __nv_bfloat162 hw; hw.x = ha; hw.y = hb;
    __nv_bfloat162 lw = __floats2bfloat162_rn(ra, rb);
    lo = *reinterpret_cast<uint32_t*>(&lw);
    return *reinterpret_cast<uint32_t*>(&hw);
}

// ---------------------------------------------------------------------------
// Merged pack kernel. Blocks [0,4096): A (c = bx&31, mt = bx>>5).
// Blocks [4096,4864): W (w = bx-4096, c = w&31, ntg = w>>5; ntg = nt*3+g).
__global__ __launch_bounds__(256) void pack_all(
    const float* __restrict__ x, const float* __restrict__ hs,
    const float* __restrict__ Wir, const float* __restrict__ Whr,
    const float* __restrict__ Wiz, const float* __restrict__ Whz,
    const float* __restrict__ Win, const float* __restrict__ Whn) {
    __shared__ float stg[32][65];
    const int bx = blockIdx.x;
    if (bx < 4096) {
        const int c = bx & 31, mt = bx >> 5;
        const float* S = (c < 16) ? x : hs;
        const int k0 = (c & 15) * 32;
        const size_t mrow = (size_t)mt * 128;
        unsigned char* hiP = g_Apack + ((size_t)(mt * 32 + c) * 2) * 8192;
        unsigned char* loP = hiP + 8192;
        #pragma unroll
        for (int it = 0; it < 8; ++it) {
            int id = it * 256 + threadIdx.x;   // 2048 float2
            int r = id >> 4, w = id & 15;
            float2 v = *reinterpret_cast<const float2*>(
                S + (mrow + r) * 512 + k0 + 2 * w);
            uint32_t lo, hi = pack_hi(v.x, v.y, lo);
            *reinterpret_cast<uint32_t*>(hiP + r * 64 + w * 4) = hi;
            *reinterpret_cast<uint32_t*>(loP + r * 64 + w * 4) = lo;
        }
    } else {
        const int w = bx - 4096;
        const int c = w & 31;
        const int ntg = w >> 5;                // 0..23 = nt*3 + g
        const int nt = ntg / 3, g = ntg % 3;
        const float* W = (c < 16)
            ? ((g == 0) ? Wir : (g == 1) ? Wiz : Win)
            : ((g == 0) ? Whr : (g == 1) ? Whz : Whn);
        const int k0 = (c & 15) * 32, n0 = nt * 64;
        #pragma unroll
        for (int it = 0; it < 8; ++it) {       // 2048 floats: 32k x 64n
            int id = it * 256 + threadIdx.x;
            int k = id >> 6, n = id & 63;
            stg[k][n] = W[(size_t)(k0 + k) * 512 + n0 + n];
        }
        __syncthreads();
        // write: [plane 2][h 2][n 64][32B]; pair p at byte (p&3)*8 + (p>>2)*4
        unsigned char* base = g_Wpack + (size_t)(ntg * 32 + c) * 8192;
        #pragma unroll
        for (int it = 0; it < 4; ++it) {       // 1024 pairs: 64n x 16kp
            int id = it * 256 + threadIdx.x;
            int n = id >> 4, kp = id & 15;
            int h = kp >> 3, pl = kp & 7;
            int off = h * 2048 + n * 32 + (pl & 3) * 8 + (pl >> 2) * 4;
            uint32_t lo, hi = pack_hi(stg[2 * kp][n], stg[2 * kp + 1][n], lo);
            *reinterpret_cast<uint32_t*>(base + off) = hi;
            *reinterpret_cast<uint32_t*>(base + 4096 + off) = lo;
        }
    }
}

// ---------------------------------------------------------------------------
// issue one A stage (chunks 2s, 2s+1): 2048 cp16, 512 threads -> 4 iters.
__device__ __forceinline__ void issue_stage(uint32_t sbase, int mt, int s) {
    const int tid = threadIdx.x;
    const unsigned char* Ac = g_Apack + ((size_t)(mt * 32 + 2 * s) * 2) * 8192;
    #pragma unroll
    for (int it = 0; it < 4; ++it) {
        int id = it * 512 + tid;               // plane(2) x row(128) x ch(8)
        int p = id >> 10, rem = id & 1023;
        int r = rem >> 3, ch = rem & 7;
        int half = ch >> 2, cho = ch & 3;
        cp16(sbase + p * PLSTR + r * ROWB + ch * 16,
             Ac + (half * 2 + p) * 8192 + r * 64 + cho * 16);
    }
}

// Load 6 B fragments (3 gates x hi/lo) for global k16-step g (clamped).
__device__ __forceinline__ void ldB(uint2 B[6], const unsigned char* bp, int g) {
    int c = g >> 1; if (c > 31) c = 31;
    const unsigned char* p = bp + (size_t)c * 8192 + (size_t)(g & 1) * 2048;
    B[0] = __ldg(reinterpret_cast<const uint2*>(p));
    B[1] = __ldg(reinterpret_cast<const uint2*>(p + 4096));
    B[2] = __ldg(reinterpret_cast<const uint2*>(p + 262144));
    B[3] = __ldg(reinterpret_cast<const uint2*>(p + 262144 + 4096));
    B[4] = __ldg(reinterpret_cast<const uint2*>(p + 524288));
    B[5] = __ldg(reinterpret_cast<const uint2*>(p + 524288 + 4096));
}

// One m32-half: 4 ldm4 + 18 mma (gate-interleaved, acc reuse distance 6).
__device__ __forceinline__ void half_mma(
    uint32_t aA, const uint2 B[6],
    float aR0[4], float aR1[4], float aZ0[4], float aZ1[4],
    float aN0[4], float aN1[4]) {
    uint32_t Ah0[4], Ah1[4], Al0[4], Al1[4];
    ldm4(Ah0, aA);
    ldm4(Ah1, aA + 16 * ROWB);
    ldm4(Al0, aA + PLSTR);
    ldm4(Al1, aA + PLSTR + 16 * ROWB);
    // term 1: Ah x Bh
    mma16(aR0, Ah0, B[0].x, B[0].y);  mma16(aR1, Ah1, B[0].x, B[0].y);
    mma16(aZ0, Ah0, B[2].x, B[2].y);  mma16(aZ1, Ah1, B[2].x, B[2].y);
    mma16(aN0, Ah0, B[4].x, B[4].y);  mma16(aN1, Ah1, B[4].x, B[4].y);
    // term 2: Al x Bh
    mma16(aR0, Al0, B[0].x, B[0].y);  mma16(aR1, Al1, B[0].x, B[0].y);
    mma16(aZ0, Al0, B[2].x, B[2].y);  mma16(aZ1, Al1, B[2].x, B[2].y);
    mma16(aN0, Al0, B[4].x, B[4].y);  mma16(aN1, Al1, B[4].x, B[4].y);
    // term 3: Ah x Bl
    mma16(aR0, Ah0, B[1].x, B[1].y);  mma16(aR1, Ah1, B[1].x, B[1].y);
    mma16(aZ0, Ah0, B[3].x, B[3].y);  mma16(aZ1, Ah1, B[3].x, B[3].y);
    mma16(aN0, Ah0, B[5].x, B[5].y);  mma16(aN1, Ah1, B[5].x, B[5].y);
}

#define STEP(KOFF, GNEXT, CUR, NXT, AN)                                   \
    do {                                                                  \
        ldB(NXT, bp, (GNEXT));                                            \
        half_mma(aA + (KOFF), CUR,                                        \
                 aR[0], aR[1], aZ[0], aZ[1], AN[0], AN[1]);               \
        half_mma(aA + (KOFF) + 32 * ROWB, CUR,                            \
                 aR[2], aR[3], aZ[2], aZ[3], AN[2], AN[3]);               \
    } while (0)

__global__ void __launch_bounds__(512, 1) gru_main(
    const float* __restrict__ hs,
    const float* __restrict__ br, const float* __restrict__ bz,
    const float* __restrict__ bn, float* __restrict__ out) {
    extern __shared__ unsigned char smem_raw[];
    const uint32_t smem = smem_u32(smem_raw);

    const int tid = threadIdx.x;
    const int wid = tid >> 5, lane = tid & 31;
    const int wm = (wid & 1) * 64;        // 0,64
    const int wn = (wid >> 1) * 8;        // 0..56
    const int nt = blockIdx.x;            // 0..7
    const int mt = blockIdx.y;            // 0..127

    const int rowA = (lane & 7) + ((lane >> 3) & 1) * 8;
    const int kbA  = (lane >> 4) * 16;
    const uint32_t aOff = (uint32_t)(wm + rowA) * ROWB + kbA;
    const unsigned char* bp = g_Wpack + (size_t)nt * 786432
        + (size_t)(wn + (lane >> 2)) * 32 + (size_t)(lane & 3) * 8;

    // Per-warp k-step rotation: warps sharing an SMSP (wid%4) get different
    // start offsets -> de-correlated LDG/LDSM phases.
    const int rot = (wid >> 2) & 3;       // 0..3
    const int g0 = rot, g1 = (rot + 1) & 3, g2 = (rot + 2) & 3, g3 = (rot + 3) & 3;
    const uint32_t o0 = (uint32_t)g0 * 32, o1 = (uint32_t)g1 * 32;
    const uint32_t o2 = (uint32_t)g2 * 32, o3 = (uint32_t)g3 * 32;

    float aR[4][4] = {}, aZ[4][4] = {}, aNi[4][4] = {}, aNh[4][4] = {};
    uint2 B0[6], B1[6];

    issue_stage(smem, mt, 0);
    cp_commit();
    issue_stage(smem + STAGE_BYTES, mt, 1);
    cp_commit();
    ldB(B0, bp, g0);

    int sidx = 0;
    for (int s = 0; s < 16; ++s) {
        cp_wait<1>();
        __syncthreads();
        const uint32_t aA = smem + sidx * STAGE_BYTES + aOff;
        const int b4 = 4 * s;
        if (s < 8) {
            STEP(o0, b4 + g1, B0, B1, aNi);
            if (s + 2 < 16) {
                int widx = sidx + 2 >= NSTAGE ? sidx + 2 - NSTAGE : sidx + 2;
                issue_stage(smem + widx * STAGE_BYTES, mt, s + 2);
                cp_commit();
            }
            STEP(o1, b4 + g2, B1, B0, aNi);
            STEP(o2, b4 + g3, B0, B1, aNi);
            STEP(o3, b4 + 4 + g0, B1, B0, aNi);
        } else {
            STEP(o0, b4 + g1, B0, B1, aNh);
            if (s + 2 < 16) {
                int widx = sidx + 2 >= NSTAGE ? sidx + 2 - NSTAGE : sidx + 2;
                issue_stage(smem + widx * STAGE_BYTES, mt, s + 2);
                cp_commit();
            }
            STEP(o1, b4 + g2, B1, B0, aNh);
            STEP(o2, b4 + g3, B0, B1, aNh);
            STEP(o3, b4 + 4 + g0, B1, B0, aNh);
        }
        sidx = (sidx + 1 >= NSTAGE) ? 0 : sidx + 1;
    }

    // ---- epilogue ----
    #pragma unroll
    for (int mtile = 0; mtile < 4; ++mtile)
    #pragma unroll
    for (int i = 0; i < 4; ++i) {
        int rr = mt * 128 + wm + mtile * 16 + (lane >> 2) + ((i >> 1) << 3);
        int cc = nt * 64 + wn + 2 * (lane & 3) + (i & 1);
        float pr = aR[mtile][i] + __ldg(br + cc);
        float pz = aZ[mtile][i] + __ldg(bz + cc);
        float rg = 1.0f / (1.0f + __expf(-pr));
        float zg = 1.0f / (1.0f + __expf(-pz));
        float ng = tanhf(aNi[mtile][i] + rg * aNh[mtile][i] + __ldg(bn + cc));
        float hv = hs[(size_t)rr * 512 + cc];
        out[(size_t)rr * 512 + cc] = (1.0f - zg) * ng + zg * hv;
    }
}

// ---------------------------------------------------------------------------
extern "C" void kernel_launch(void* const* d_in, const int* in_sizes, int n_in,
                              void* d_out, int out_size) {
    (void)in_sizes; (void)n_in; (void)out_size;
    const float* x   = (const float*)d_in[0];
    const float* h   = (const float*)d_in[1];
    const float* Wir = (const float*)d_in[2];
    const float* Whr = (const float*)d_in[3];
    const float* br  = (const float*)d_in[4];
    const float* Wiz = (const float*)d_in[5];
    const float* Whz = (const float*)d_in[6];
    const float* bz  = (const float*)d_in[7];
    const float* Win = (const float*)d_in[8];
    const float* Whn = (const float*)d_in[9];
    const float* bn  = (const float*)d_in[10];

    static_assert(SMEM_TOTAL == 110592, "smem layout");
    cudaFuncSetAttribute(gru_main, cudaFuncAttributeMaxDynamicSharedMemorySize,
                         SMEM_TOTAL);
    cudaFuncSetAttribute(gru_main, cudaFuncAttributePreferredSharedMemoryCarveout,
                         cudaSharedmemCarveoutMaxShared);

    pack_all<<<4864, 256>>>(x, h, Wir, Whr, Wiz, Whz, Win, Whn);
    gru_main<<<dim3(NT_COUNT, MT_COUNT), 512, SMEM_TOTAL>>>(
        h, br, bz, bn, (float*)d_out);
}

// round 12
// speedup vs baseline: 1.1631x; 1.1631x over previous
#include <cuda_runtime.h>
#include <cuda_bf16.h>
#include <cstdint>

// ===========================================================================
// GRU cell via mma.sync (sm_103 non-'a' target: tcgen05 unavailable).
// 3-term bf16 split: C = Ah*Bh + Al*Bh + Ah*Bl  (~2^-17 effective precision).
// R12: R10's mainloop (B direct from L2 via LDG.64, A via cp.async) in a
// 256-thread M64xN64 CTA -> 2 independent CTAs/SM. Same 16 warps/SM as R10
// but the two CTAs' barriers de-phase naturally, covering each other's
// post-barrier LDG/LDSM heads on the tensor pipe.
//   8 warps (1m x 8n), warp tile m64 x n8 (64 acc regs, as R10).
//   3-stage cp.async A pipeline (18.4KB/stage), B double-buffered in regs.
// ===========================================================================

#define NT_COUNT 8           // 512 / 64
#define MT_COUNT 256         // 16384 / 64
#define NSTAGE 3

// packed A: [mt 256][chunk 32][plane 2][row 64][64B]  = 64 MB
__device__ __align__(128) unsigned char g_Apack[256u * 32u * 2u * 64u * 64u];
// packed W: [nt 8][gate 3][chunk 32][plane 2][k16half 2][n 64][32B] = 6 MB
//   32B per (n, k16): pairs stored as (q, q+4) adjacent -> one LDG.64 = {b0,b1}
__device__ __align__(128) unsigned char g_Wpack[8u * 3u * 32u * 2u * 2u * 64u * 32u];

// smem: A only. 144B row stride (36 banks -> conflict-free ldmatrix):
//   plane p: p*9216 + r*144   (64 rows, 128B data = k64)
#define ROWB 144
#define PLSTR 9216
#define STAGE_BYTES 18432
#define SMEM_TOTAL (NSTAGE * STAGE_BYTES)   // 55296 -> 2 CTAs/SM

__device__ __forceinline__ uint32_t smem_u32(const void* p) {
    uint32_t a;
    asm("{ .reg .u64 t; cvta.to.shared.u64 t, %1; cvt.u32.u64 %0, t; }"
        : "=r"(a) : "l"(p));
    return a;
}

__device__ __forceinline__ void cp16(uint32_t dst, const void* src) {
    asm volatile("cp.async.cg.shared.global [%0], [%1], 16;"
                 :: "r"(dst), "l"(src) : "memory");
}
__device__ __forceinline__ void cp_commit() {
    asm volatile("cp.async.commit_group;" ::: "memory");
}
template <int N> __device__ __forceinline__ void cp_wait() {
    asm volatile("cp.async.wait_group %0;" :: "n"(N) : "memory");
}

__device__ __forceinline__ void ldm4(uint32_t r[4], uint32_t addr) {
    asm volatile("ldmatrix.sync.aligned.m8n8.x4.shared.b16 {%0,%1,%2,%3}, [%4];"
                 : "=r"(r[0]), "=r"(r[1]), "=r"(r[2]), "=r"(r[3]) : "r"(addr));
}

__device__ __forceinline__ void mma16(float c[4], const uint32_t a[4],
                                      uint32_t b0, uint32_t b1) {
    asm volatile(
        "mma.sync.aligned.m16n8k16.row.col.f32.bf16.bf16.f32 "
        "{%0,%1,%2,%3}, {%4,%5,%6,%7}, {%8,%9}, {%0,%1,%2,%3};\n"
        : "+f"(c[0]), "+f"(c[1]), "+f"(c[2]), "+f"(c[3])
        : "r"(a[0]), "r"(a[1]), "r"(a[2]), "r"(a[3]), "r"(b0), "r"(b1));
}

__device__ __forceinline__ uint32_t pack_hi(float a, float b, uint32_t& lo) {
    __nv_bfloat16 ha = __float2bfloat16(a);
    __nv_bfloat16 hb = __float2bfloat16(b);
    float ra = a - __bfloat162float(ha);
    float rb = b - __bfloat162float(hb);
    __nv_bfloat162 hw; hw.x = ha; hw.y = hb;
    __nv_bfloat162 lw = __floats2bfloat162_rn(ra, rb);
    lo = *reinterpret_cast<uint32_t*>(&lw);
    return *reinterpret_cast<uint32_t*>(&hw);
}

// ---------------------------------------------------------------------------
// Merged pack kernel. Blocks [0,4096): A (c = bx&31, mt128 = bx>>5 covers two
// 64-row tiles). Blocks [4096,4864): W (w = bx-4096, c = w&31, ntg = w>>5).
__global__ __launch_bounds__(256) void pack_all(
    const float* __restrict__ x, const float* __restrict__ hs,
    const float* __restrict__ Wir, const float* __restrict__ Whr,
    const float* __restrict__ Wiz, const float* __restrict__ Whz,
    const float* __restrict__ Win, const float* __restrict__ Whn) {
    __shared__ float stg[32][65];
    const int bx = blockIdx.x;
    if (bx < 4096) {
        const int c = bx & 31, mt128 = bx >> 5;
        const float* S = (c < 16) ? x : hs;
        const int k0 = (c & 15) * 32;
        const size_t mrow = (size_t)mt128 * 128;
        #pragma unroll
        for (int it = 0; it < 8; ++it) {
            int id = it * 256 + threadIdx.x;   // 2048 float2
            int r = id >> 4, w = id & 15;      // r in [0,128)
            float2 v = *reinterpret_cast<const float2*>(
                S + (mrow + r) * 512 + k0 + 2 * w);
            uint32_t lo, hi = pack_hi(v.x, v.y, lo);
            int mt64 = mt128 * 2 + (r >> 6);
            int rl = r & 63;
            unsigned char* hiP = g_Apack + ((size_t)(mt64 * 32 + c) * 2) * 4096;
            *reinterpret_cast<uint32_t*>(hiP + rl * 64 + w * 4) = hi;
            *reinterpret_cast<uint32_t*>(hiP + 4096 + rl * 64 + w * 4) = lo;
        }
    } else {
        const int w = bx - 4096;
        const int c = w & 31;
        const int ntg = w >> 5;                // 0..23 = nt*3 + g
        const int nt = ntg / 3, g = ntg % 3;
        const float* W = (c < 16)
            ? ((g == 0) ? Wir : (g == 1) ? Wiz : Win)
            : ((g == 0) ? Whr : (g == 1) ? Whz : Whn);
        const int k0 = (c & 15) * 32, n0 = nt * 64;
        #pragma unroll
        for (int it = 0; it < 8; ++it) {       // 2048 floats: 32k x 64n
            int id = it * 256 + threadIdx.x;
            int k = id >> 6, n = id & 63;
            stg[k][n] = W[(size_t)(k0 + k) * 512 + n0 + n];
        }
        __syncthreads();
        // write: [plane 2][h 2][n 64][32B]; pair p at byte (p&3)*8 + (p>>2)*4
        unsigned char* base = g_Wpack + (size_t)(ntg * 32 + c) * 8192;
        #pragma unroll
        for (int it = 0; it < 4; ++it) {       // 1024 pairs: 64n x 16kp
            int id = it * 256 + threadIdx.x;
            int n = id >> 4, kp = id & 15;
            int h = kp >> 3, pl = kp & 7;
            int off = h * 2048 + n * 32 + (pl & 3) * 8 + (pl >> 2) * 4;
            uint32_t lo, hi = pack_hi(stg[2 * kp][n], stg[2 * kp + 1][n], lo);
            *reinterpret_cast<uint32_t*>(base + off) = hi;
            *reinterpret_cast<uint32_t*>(base + 4096 + off) = lo;
        }
    }
}

// ---------------------------------------------------------------------------
// issue one A stage (chunks 2s, 2s+1): 1024 cp16, 256 threads -> 4 iters.
__device__ __forceinline__ void issue_stage(uint32_t sbase, int mt, int s) {
    const int tid = threadIdx.x;
    const unsigned char* Ac = g_Apack + ((size_t)(mt * 32 + 2 * s) * 2) * 4096;
    #pragma unroll
    for (int it = 0; it < 4; ++it) {
        int id = it * 256 + tid;               // plane(2) x row(64) x ch(8)
        int p = id >> 9, rem = id & 511;
        int r = rem >> 3, ch = rem & 7;
        int half = ch >> 2, cho = ch & 3;
        cp16(sbase + p * PLSTR + r * ROWB + ch * 16,
             Ac + (half * 2 + p) * 4096 + r * 64 + cho * 16);
    }
}

// Load 6 B fragments (3 gates x hi/lo) for global k16-step g (clamped).
__device__ __forceinline__ void ldB(uint2 B[6], const unsigned char* bp, int g) {
    int c = g >> 1; if (c > 31) c = 31;
    const unsigned char* p = bp + (size_t)c * 8192 + (size_t)(g & 1) * 2048;
    B[0] = __ldg(reinterpret_cast<const uint2*>(p));
    B[1] = __ldg(reinterpret_cast<const uint2*>(p + 4096));
    B[2] = __ldg(reinterpret_cast<const uint2*>(p + 262144));
    B[3] = __ldg(reinterpret_cast<const uint2*>(p + 262144 + 4096));
    B[4] = __ldg(reinterpret_cast<const uint2*>(p + 524288));
    B[5] = __ldg(reinterpret_cast<const uint2*>(p + 524288 + 4096));
}

// One m32-half: 4 ldm4 + 18 mma (gate-interleaved, acc reuse distance 6).
__device__ __forceinline__ void half_mma(
    uint32_t aA, const uint2 B[6],
    float aR0[4], float aR1[4], float aZ0[4], float aZ1[4],
    float aN0[4], float aN1[4]) {
    uint32_t Ah0[4], Ah1[4], Al0[4], Al1[4];
    ldm4(Ah0, aA);
    ldm4(Ah1, aA + 16 * ROWB);
    ldm4(Al0, aA + PLSTR);
    ldm4(Al1, aA + PLSTR + 16 * ROWB);
    // term 1: Ah x Bh
    mma16(aR0, Ah0, B[0].x, B[0].y);  mma16(aR1, Ah1, B[0].x, B[0].y);
    mma16(aZ0, Ah0, B[2].x, B[2].y);  mma16(aZ1, Ah1, B[2].x, B[2].y);
    mma16(aN0, Ah0, B[4].x, B[4].y);  mma16(aN1, Ah1, B[4].x, B[4].y);
    // term 2: Al x Bh
    mma16(aR0, Al0, B[0].x, B[0].y);  mma16(aR1, Al1, B[0].x, B[0].y);
    mma16(aZ0, Al0, B[2].x, B[2].y);  mma16(aZ1, Al1, B[2].x, B[2].y);
    mma16(aN0, Al0, B[4].x, B[4].y);  mma16(aN1, Al1, B[4].x, B[4].y);
    // term 3: Ah x Bl
    mma16(aR0, Ah0, B[1].x, B[1].y);  mma16(aR1, Ah1, B[1].x, B[1].y);
    mma16(aZ0, Ah0, B[3].x, B[3].y);  mma16(aZ1, Ah1, B[3].x, B[3].y);
    mma16(aN0, Ah0, B[5].x, B[5].y);  mma16(aN1, Ah1, B[5].x, B[5].y);
}

#define STEP(KS, CUR, NXT, AN)                                            \
    do {                                                                  \
        ldB(NXT, bp, 4 * s + (KS) + 1);                                   \
        half_mma(aA + (KS) * 32, CUR,                                     \
                 aR[0], aR[1], aZ[0], aZ[1], AN[0], AN[1]);               \
        half_mma(aA + (KS) * 32 + 32 * ROWB, CUR,                         \
                 aR[2], aR[3], aZ[2], aZ[3], AN[2], AN[3]);               \
    } while (0)

__global__ void __launch_bounds__(256, 2) gru_main(
    const float* __restrict__ hs,
    const float* __restrict__ br, const float* __restrict__ bz,
    const float* __restrict__ bn, float* __restrict__ out) {
    extern __shared__ unsigned char smem_raw[];
    const uint32_t smem = smem_u32(smem_raw);

    const int tid = threadIdx.x;
    const int wid = tid >> 5, lane = tid & 31;
    const int wn = wid * 8;               // 0..56
    const int nt = blockIdx.x;            // 0..7
    const int mt = blockIdx.y;            // 0..255

    const int rowA = (lane & 7) + ((lane >> 3) & 1) * 8;
    const int kbA  = (lane >> 4) * 16;
    const uint32_t aOff = (uint32_t)rowA * ROWB + kbA;
    const unsigned char* bp = g_Wpack + (size_t)nt * 786432
        + (size_t)(wn + (lane >> 2)) * 32 + (size_t)(lane & 3) * 8;

    float aR[4][4] = {}, aZ[4][4] = {}, aNi[4][4] = {}, aNh[4][4] = {};
    uint2 B0[6], B1[6];

    issue_stage(smem, mt, 0);
    cp_commit();
    issue_stage(smem + STAGE_BYTES, mt, 1);
    cp_commit();
    ldB(B0, bp, 0);

    int sidx = 0;
    for (int s = 0; s < 16; ++s) {
        if (s == 15) cp_wait<0>(); else cp_wait<1>();
        __syncthreads();
        const uint32_t aA = smem + sidx * STAGE_BYTES + aOff;
        if (s < 8) {
            STEP(0, B0, B1, aNi);
            if (s + 2 < 16) {
                int widx = sidx + 2 >= NSTAGE ? sidx + 2 - NSTAGE : sidx + 2;
                issue_stage(smem + widx * STAGE_BYTES, mt, s + 2);
                cp_commit();
            }
            STEP(1, B1, B0, aNi);
            STEP(2, B0, B1, aNi);
            STEP(3, B1, B0, aNi);
        } else {
            STEP(0, B0, B1, aNh);
            if (s + 2 < 16) {
                int widx = sidx + 2 >= NSTAGE ? sidx + 2 - NSTAGE : sidx + 2;
                issue_stage(smem + widx * STAGE_BYTES, mt, s + 2);
                cp_commit();
            }
            STEP(1, B1, B0, aNh);
            STEP(2, B0, B1, aNh);
            STEP(3, B1, B0, aNh);
        }
        sidx = (sidx + 1 >= NSTAGE) ? 0 : sidx + 1;
    }

    // ---- epilogue ----
    #pragma unroll
    for (int mtile = 0; mtile < 4; ++mtile)
    #pragma unroll
    for (int i = 0; i < 4; ++i) {
        int rr = mt * 64 + mtile * 16 + (lane >> 2) + ((i >> 1) << 3);
        int cc = nt * 64 + wn + 2 * (lane & 3) + (i & 1);
        float pr = aR[mtile][i] + __ldg(br + cc);
        float pz = aZ[mtile][i] + __ldg(bz + cc);
        float rg = 1.0f / (1.0f + __expf(-pr));
        float zg = 1.0f / (1.0f + __expf(-pz));
        float ng = tanhf(aNi[mtile][i] + rg * aNh[mtile][i] + __ldg(bn + cc));
        float hv = hs[(size_t)rr * 512 + cc];
        out[(size_t)rr * 512 + cc] = (1.0f - zg) * ng + zg * hv;
    }
}

// ---------------------------------------------------------------------------
extern "C" void kernel_launch(void* const* d_in, const int* in_sizes, int n_in,
                              void* d_out, int out_size) {
    (void)in_sizes; (void)n_in; (void)out_size;
    const float* x   = (const float*)d_in[0];
    const float* h   = (const float*)d_in[1];
    const float* Wir = (const float*)d_in[2];
    const float* Whr = (const float*)d_in[3];
    const float* br  = (const float*)d_in[4];
    const float* Wiz = (const float*)d_in[5];
    const float* Whz = (const float*)d_in[6];
    const float* bz  = (const float*)d_in[7];
    const float* Win = (const float*)d_in[8];
    const float* Whn = (const float*)d_in[9];
    const float* bn  = (const float*)d_in[10];

    static_assert(SMEM_TOTAL == 55296, "smem layout");
    cudaFuncSetAttribute(gru_main, cudaFuncAttributeMaxDynamicSharedMemorySize,
                         SMEM_TOTAL);
    cudaFuncSetAttribute(gru_main, cudaFuncAttributePreferredSharedMemoryCarveout,
                         cudaSharedmemCarveoutMaxShared);

    pack_all<<<4864, 256>>>(x, h, Wir, Whr, Wiz, Whz, Win, Whn);
    gru_main<<<dim3(NT_COUNT, MT_COUNT), 256, SMEM_TOTAL>>>(
        h, br, bz, bn, (float*)d_out);
}

// round 13
// speedup vs baseline: 1.2429x; 1.0686x over previous
#include <cuda_runtime.h>
#include <cuda_bf16.h>
#include <cstdint>

// ===========================================================================
// GRU cell via mma.sync (sm_103 non-'a' target: tcgen05 unavailable).
// 3-term bf16 split: C = Ah*Bh + Al*Bh + Ah*Bl  (~2^-17 effective precision).
// R13 = R12 (M64xN64 CTA, 2 CTAs/SM de-phased, B direct from L2 via LDG.64)
//       + K=128 pipeline stages -> 8 barriers per CTA (was 16).
//   8 warps (1m x 8n), warp tile m64 x n8 (64 acc regs).
//   3-stage cp.async A pipeline (34KB/stage), B double-buffered in regs.
// ===========================================================================

#define NT_COUNT 8           // 512 / 64
#define MT_COUNT 256         // 16384 / 64
#define NSTAGE 3

// packed A: [mt 256][chunk 32][plane 2][row 64][64B]  = 64 MB
__device__ __align__(128) unsigned char g_Apack[256u * 32u * 2u * 64u * 64u];
// packed W: [nt 8][gate 3][chunk 32][plane 2][k16half 2][n 64][32B] = 6 MB
//   32B per (n, k16): pairs stored as (q, q+4) adjacent -> one LDG.64 = {b0,b1}
__device__ __align__(128) unsigned char g_Wpack[8u * 3u * 32u * 2u * 2u * 64u * 32u];

// smem: A only, K=128 per stage. 272B row stride (68 banks: consecutive rows
// shift 4 banks -> 8-row ldmatrix covers banks 0..31 exactly, conflict-free).
//   plane p: p*17408 + r*272   (64 rows, 256B data = k128)
#define ROWB 272
#define PLSTR 17408
#define STAGE_BYTES 34816
#define SMEM_TOTAL (NSTAGE * STAGE_BYTES)   // 104448 -> 2 CTAs/SM (204KB)

__device__ __forceinline__ uint32_t smem_u32(const void* p) {
    uint32_t a;
    asm("{ .reg .u64 t; cvta.to.shared.u64 t, %1; cvt.u32.u64 %0, t; }"
        : "=r"(a) : "l"(p));
    return a;
}

__device__ __forceinline__ void cp16(uint32_t dst, const void* src) {
    asm volatile("cp.async.cg.shared.global [%0], [%1], 16;"
                 :: "r"(dst), "l"(src) : "memory");
}
__device__ __forceinline__ void cp_commit() {
    asm volatile("cp.async.commit_group;" ::: "memory");
}
template <int N> __device__ __forceinline__ void cp_wait() {
    asm volatile("cp.async.wait_group %0;" :: "n"(N) : "memory");
}

__device__ __forceinline__ void ldm4(uint32_t r[4], uint32_t addr) {
    asm volatile("ldmatrix.sync.aligned.m8n8.x4.shared.b16 {%0,%1,%2,%3}, [%4];"
                 : "=r"(r[0]), "=r"(r[1]), "=r"(r[2]), "=r"(r[3]) : "r"(addr));
}

__device__ __forceinline__ void mma16(float c[4], const uint32_t a[4],
                                      uint32_t b0, uint32_t b1) {
    asm volatile(
        "mma.sync.aligned.m16n8k16.row.col.f32.bf16.bf16.f32 "
        "{%0,%1,%2,%3}, {%4,%5,%6,%7}, {%8,%9}, {%0,%1,%2,%3};\n"
        : "+f"(c[0]), "+f"(c[1]), "+f"(c[2]), "+f"(c[3])
        : "r"(a[0]), "r"(a[1]), "r"(a[2]), "r"(a[3]), "r"(b0), "r"(b1));
}

__device__ __forceinline__ uint32_t pack_hi(float a, float b, uint32_t& lo) {
    __nv_bfloat16 ha = __float2bfloat16(a);
    __nv_bfloat16 hb = __float2bfloat16(b);
    float ra = a - __bfloat162float(ha);
    float rb = b - __bfloat162float(hb);
    __nv_bfloat162 hw; hw.x = ha; hw.y = hb;
    __nv_bfloat162 lw = __floats2bfloat162_rn(ra, rb);
    lo = *reinterpret_cast<uint32_t*>(&lw);
    return *reinterpret_cast<uint32_t*>(&hw);
}

// ---------------------------------------------------------------------------
// Merged pack kernel. Blocks [0,4096): A (c = bx&31, mt128 = bx>>5 covers two
// 64-row tiles). Blocks [4096,4864): W (w = bx-4096, c = w&31, ntg = w>>5).
__global__ __launch_bounds__(256) void pack_all(
    const float* __restrict__ x, const float* __restrict__ hs,
    const float* __restrict__ Wir, const float* __restrict__ Whr,
    const float* __restrict__ Wiz, const float* __restrict__ Whz,
    const float* __restrict__ Win, const float* __restrict__ Whn) {
    __shared__ float stg[32][65];
    const int bx = blockIdx.x;
    if (bx < 4096) {
        const int c = bx & 31, mt128 = bx >> 5;
        const float* S = (c < 16) ? x : hs;
        const int k0 = (c & 15) * 32;
        const size_t mrow = (size_t)mt128 * 128;
        #pragma unroll
        for (int it = 0; it < 8; ++it) {
            int id = it * 256 + threadIdx.x;   // 2048 float2
            int r = id >> 4, w = id & 15;      // r in [0,128)
            float2 v = *reinterpret_cast<const float2*>(
                S + (mrow + r) * 512 + k0 + 2 * w);
            uint32_t lo, hi = pack_hi(v.x, v.y, lo);
            int mt64 = mt128 * 2 + (r >> 6);
            int rl = r & 63;
            unsigned char* hiP = g_Apack + ((size_t)(mt64 * 32 + c) * 2) * 4096;
            *reinterpret_cast<uint32_t*>(hiP + rl * 64 + w * 4) = hi;
            *reinterpret_cast<uint32_t*>(hiP + 4096 + rl * 64 + w * 4) = lo;
        }
    } else {
        const int w = bx - 4096;
        const int c = w & 31;
        const int ntg = w >> 5;                // 0..23 = nt*3 + g
        const int nt = ntg / 3, g = ntg % 3;
        const float* W = (c < 16)
            ? ((g == 0) ? Wir : (g == 1) ? Wiz : Win)
            : ((g == 0) ? Whr : (g == 1) ? Whz : Whn);
        const int k0 = (c & 15) * 32, n0 = nt * 64;
        #pragma unroll
        for (int it = 0; it < 8; ++it) {       // 2048 floats: 32k x 64n
            int id = it * 256 + threadIdx.x;
            int k = id >> 6, n = id & 63;
            stg[k][n] = W[(size_t)(k0 + k) * 512 + n0 + n];
        }
        __syncthreads();
        // write: [plane 2][h 2][n 64][32B]; pair p at byte (p&3)*8 + (p>>2)*4
        unsigned char* base = g_Wpack + (size_t)(ntg * 32 + c) * 8192;
        #pragma unroll
        for (int it = 0; it < 4; ++it) {       // 1024 pairs: 64n x 16kp
            int id = it * 256 + threadIdx.x;
            int n = id >> 4, kp = id & 15;
            int h = kp >> 3, pl = kp & 7;
            int off = h * 2048 + n * 32 + (pl & 3) * 8 + (pl >> 2) * 4;
            uint32_t lo, hi = pack_hi(stg[2 * kp][n], stg[2 * kp + 1][n], lo);
            *reinterpret_cast<uint32_t*>(base + off) = hi;
            *reinterpret_cast<uint32_t*>(base + 4096 + off) = lo;
        }
    }
}

// ---------------------------------------------------------------------------
// issue one A stage (chunks 4s..4s+3): 2048 cp16, 256 threads -> 8 iters.
// SMEM row holds k128: byte range [cl*64, cl*64+64) from chunk 4s+cl.
__device__ __forceinline__ void issue_stage(uint32_t sbase, int mt, int s) {
    const int tid = threadIdx.x;
    const unsigned char* Ac = g_Apack + ((size_t)(mt * 32 + 4 * s) * 2) * 4096;
    #pragma unroll
    for (int it = 0; it < 8; ++it) {
        int id = it * 256 + tid;               // plane(2) x row(64) x ch(16)
        int p = id >> 10, rem = id & 1023;
        int r = rem >> 4, ch = rem & 15;
        int cl = ch >> 2, cho = ch & 3;
        cp16(sbase + p * PLSTR + r * ROWB + ch * 16,
             Ac + ((size_t)cl * 2 + p) * 4096 + r * 64 + cho * 16);
    }
}

// Load 6 B fragments (3 gates x hi/lo) for global k16-step g (clamped).
__device__ __forceinline__ void ldB(uint2 B[6], const unsigned char* bp, int g) {
    int c = g >> 1; if (c > 31) c = 31;
    const unsigned char* p = bp + (size_t)c * 8192 + (size_t)(g & 1) * 2048;
    B[0] = __ldg(reinterpret_cast<const uint2*>(p));
    B[1] = __ldg(reinterpret_cast<const uint2*>(p + 4096));
    B[2] = __ldg(reinterpret_cast<const uint2*>(p + 262144));
    B[3] = __ldg(reinterpret_cast<const uint2*>(p + 262144 + 4096));
    B[4] = __ldg(reinterpret_cast<const uint2*>(p + 524288));
    B[5] = __ldg(reinterpret_cast<const uint2*>(p + 524288 + 4096));
}

// One m32-half: 4 ldm4 + 18 mma (gate-interleaved, acc reuse distance 6).
__device__ __forceinline__ void half_mma(
    uint32_t aA, const uint2 B[6],
    float aR0[4], float aR1[4], float aZ0[4], float aZ1[4],
    float aN0[4], float aN1[4]) {
    uint32_t Ah0[4], Ah1[4], Al0[4], Al1[4];
    ldm4(Ah0, aA);
    ldm4(Ah1, aA + 16 * ROWB);
    ldm4(Al0, aA + PLSTR);
    ldm4(Al1, aA + PLSTR + 16 * ROWB);
    // term 1: Ah x Bh
    mma16(aR0, Ah0, B[0].x, B[0].y);  mma16(aR1, Ah1, B[0].x, B[0].y);
    mma16(aZ0, Ah0, B[2].x, B[2].y);  mma16(aZ1, Ah1, B[2].x, B[2].y);
    mma16(aN0, Ah0, B[4].x, B[4].y);  mma16(aN1, Ah1, B[4].x, B[4].y);
    // term 2: Al x Bh
    mma16(aR0, Al0, B[0].x, B[0].y);  mma16(aR1, Al1, B[0].x, B[0].y);
    mma16(aZ0, Al0, B[2].x, B[2].y);  mma16(aZ1, Al1, B[2].x, B[2].y);
    mma16(aN0, Al0, B[4].x, B[4].y);  mma16(aN1, Al1, B[4].x, B[4].y);
    // term 3: Ah x Bl
    mma16(aR0, Ah0, B[1].x, B[1].y);  mma16(aR1, Ah1, B[1].x, B[1].y);
    mma16(aZ0, Ah0, B[3].x, B[3].y);  mma16(aZ1, Ah1, B[3].x, B[3].y);
    mma16(aN0, Ah0, B[5].x, B[5].y);  mma16(aN1, Ah1, B[5].x, B[5].y);
}

// Step j of stage s: uses CUR B regs, prefetches NXT for step 8s+j+1.
#define STEP(J, CUR, NXT, AN)                                             \
    do {                                                                  \
        ldB(NXT, bp, 8 * s + (J) + 1);                                    \
        half_mma(aA + (J) * 32, CUR,                                      \
                 aR[0], aR[1], aZ[0], aZ[1], AN[0], AN[1]);               \
        half_mma(aA + (J) * 32 + 32 * ROWB, CUR,                          \
                 aR[2], aR[3], aZ[2], aZ[3], AN[2], AN[3]);               \
    } while (0)

__global__ void __launch_bounds__(256, 2) gru_main(
    const float* __restrict__ hs,
    const float* __restrict__ br, const float* __restrict__ bz,
    const float* __restrict__ bn, float* __restrict__ out) {
    extern __shared__ unsigned char smem_raw[];
    const uint32_t smem = smem_u32(smem_raw);

    const int tid = threadIdx.x;
    const int wid = tid >> 5, lane = tid & 31;
    const int wn = wid * 8;               // 0..56
    const int nt = blockIdx.x;            // 0..7
    const int mt = blockIdx.y;            // 0..255

    const int rowA = (lane & 7) + ((lane >> 3) & 1) * 8;
    const int kbA  = (lane >> 4) * 16;
    const uint32_t aOff = (uint32_t)rowA * ROWB + kbA;
    const unsigned char* bp = g_Wpack + (size_t)nt * 786432
        + (size_t)(wn + (lane >> 2)) * 32 + (size_t)(lane & 3) * 8;

    float aR[4][4] = {}, aZ[4][4] = {}, aNi[4][4] = {}, aNh[4][4] = {};
    uint2 B0[6], B1[6];

    issue_stage(smem, mt, 0);
    cp_commit();
    issue_stage(smem + STAGE_BYTES, mt, 1);
    cp_commit();
    ldB(B0, bp, 0);

    int sidx = 0;
    for (int s = 0; s < 8; ++s) {
        if (s == 7) cp_wait<0>(); else cp_wait<1>();
        __syncthreads();
        const uint32_t aA = smem + sidx * STAGE_BYTES + aOff;
        if (s < 4) {
            STEP(0, B0, B1, aNi);
            if (s + 2 < 8) {
                int widx = sidx + 2 >= NSTAGE ? sidx + 2 - NSTAGE : sidx + 2;
                issue_stage(smem + widx * STAGE_BYTES, mt, s + 2);
                cp_commit();
            }
            STEP(1, B1, B0, aNi);
            STEP(2, B0, B1, aNi);
            STEP(3, B1, B0, aNi);
            STEP(4, B0, B1, aNi);
            STEP(5, B1, B0, aNi);
            STEP(6, B0, B1, aNi);
            STEP(7, B1, B0, aNi);
        } else {
            STEP(0, B0, B1, aNh);
            if (s + 2 < 8) {
                int widx = sidx + 2 >= NSTAGE ? sidx + 2 - NSTAGE : sidx + 2;
                issue_stage(smem + widx * STAGE_BYTES, mt, s + 2);
                cp_commit();
            }
            STEP(1, B1, B0, aNh);
            STEP(2, B0, B1, aNh);
            STEP(3, B1, B0, aNh);
            STEP(4, B0, B1, aNh);
            STEP(5, B1, B0, aNh);
            STEP(6, B0, B1, aNh);
            STEP(7, B1, B0, aNh);
        }
        sidx = (sidx + 1 >= NSTAGE) ? 0 : sidx + 1;
    }

    // ---- epilogue ----
    #pragma unroll
    for (int mtile = 0; mtile < 4; ++mtile)
    #pragma unroll
    for (int i = 0; i < 4; ++i) {
        int rr = mt * 64 + mtile * 16 + (lane >> 2) + ((i >> 1) << 3);
        int cc = nt * 64 + wn + 2 * (lane & 3) + (i & 1);
        float pr = aR[mtile][i] + __ldg(br + cc);
        float pz = aZ[mtile][i] + __ldg(bz + cc);
        float rg = 1.0f / (1.0f + __expf(-pr));
        float zg = 1.0f / (1.0f + __expf(-pz));
        float ng = tanhf(aNi[mtile][i] + rg * aNh[mtile][i] + __ldg(bn + cc));
        float hv = hs[(size_t)rr * 512 + cc];
        out[(size_t)rr * 512 + cc] = (1.0f - zg) * ng + zg * hv;
    }
}

// ---------------------------------------------------------------------------
extern "C" void kernel_launch(void* const* d_in, const int* in_sizes, int n_in,
                              void* d_out, int out_size) {
    (void)in_sizes; (void)n_in; (void)out_size;
    const float* x   = (const float*)d_in[0];
    const float* h   = (const float*)d_in[1];
    const float* Wir = (const float*)d_in[2];
    const float* Whr = (const float*)d_in[3];
    const float* br  = (const float*)d_in[4];
    const float* Wiz = (const float*)d_in[5];
    const float* Whz = (const float*)d_in[6];
    const float* bz  = (const float*)d_in[7];
    const float* Win = (const float*)d_in[8];
    const float* Whn = (const float*)d_in[9];
    const float* bn  = (const float*)d_in[10];

    static_assert(SMEM_TOTAL == 104448, "smem layout");
    cudaFuncSetAttribute(gru_main, cudaFuncAttributeMaxDynamicSharedMemorySize,
                         SMEM_TOTAL);
    cudaFuncSetAttribute(gru_main, cudaFuncAttributePreferredSharedMemoryCarveout,
                         cudaSharedmemCarveoutMaxShared);

    pack_all<<<4864, 256>>>(x, h, Wir, Whr, Wiz, Whz, Win, Whn);
    gru_main<<<dim3(NT_COUNT, MT_COUNT), 256, SMEM_TOTAL>>>(
        h, br, bz, bn, (float*)d_out);
}

// round 14
// speedup vs baseline: 1.2521x; 1.0074x over previous
#include <cuda_runtime.h>
#include <cuda_bf16.h>
#include <cstdint>

// ===========================================================================
// GRU cell via mma.sync (sm_103 non-'a' target: tcgen05 unavailable).
// 3-term bf16 split: C = Ah*Bh + Al*Bh + Ah*Bl  (~2^-17 effective precision).
// R14: ZERO smem / ZERO barriers. A is pre-packed in per-lane mma fragment
// order -> each thread's a[4] is one aligned LDG.128 served from L1 (8 warps
// of the CTA share lines; first touch hits L2 where the pack is resident).
// B direct from L2 via LDG.64 double-buffered (R10-13 path, unchanged).
//   CTA tile M=64 x N=64, 256 threads = 8 warps (1m x 8n), warp m64 x n8.
//   2 CTAs/SM (register-bound), warps fully independent.
// ===========================================================================

#define NT_COUNT 8           // 512 / 64
#define MT_COUNT 256         // 16384 / 64

// packed A fragments: [mt 256][k16step 64][mtile 4][plane 2][lane 32][16B]
//   = 256 * 64 * 4096 B = 64 MB.  Step s<32 from x, s>=32 from h.
__device__ __align__(128) unsigned char g_Afrag[256u * 64u * 4096u];
// packed W: [nt 8][gate 3][chunk 32][plane 2][k16half 2][n 64][32B] = 6 MB
//   32B per (n, k16): pairs stored as (q, q+4) adjacent -> one LDG.64 = {b0,b1}
__device__ __align__(128) unsigned char g_Wpack[8u * 3u * 32u * 2u * 2u * 64u * 32u];

__device__ __forceinline__ void mma16(float c[4], const uint32_t a[4],
                                      uint32_t b0, uint32_t b1) {
    asm volatile(
        "mma.sync.aligned.m16n8k16.row.col.f32.bf16.bf16.f32 "
        "{%0,%1,%2,%3}, {%4,%5,%6,%7}, {%8,%9}, {%0,%1,%2,%3};\n"
        : "+f"(c[0]), "+f"(c[1]), "+f"(c[2]), "+f"(c[3])
        : "r"(a[0]), "r"(a[1]), "r"(a[2]), "r"(a[3]), "r"(b0), "r"(b1));
}

__device__ __forceinline__ uint32_t pack_hi(float a, float b, uint32_t& lo) {
    __nv_bfloat16 ha = __float2bfloat16(a);
    __nv_bfloat16 hb = __float2bfloat16(b);
    float ra = a - __bfloat162float(ha);
    float rb = b - __bfloat162float(hb);
    __nv_bfloat162 hw; hw.x = ha; hw.y = hb;
    __nv_bfloat162 lw = __floats2bfloat162_rn(ra, rb);
    lo = *reinterpret_cast<uint32_t*>(&lw);
    return *reinterpret_cast<uint32_t*>(&hw);
}

// ---------------------------------------------------------------------------
// Merged pack kernel.
// Blocks [0,2048): A fragments. Block = (mt = bx>>3, step-group sg = bx&7),
//   covers steps sg*8 .. sg*8+7. Per step: 512 items (mtile,lane,word); each
//   item reads one float2 and writes hi word (plane0) + lo word (plane1).
//   Fragment word w for (row r, kq): w0=(r,kq) w1=(r+8,kq) w2=(r,kq+8)
//   w3=(r+8,kq+8), matching the m16n8k16 A register layout.
// Blocks [2048,2816): W part (w = bx-2048, c = w&31, ntg = w>>5 = nt*3+g).
__global__ __launch_bounds__(256) void pack_all(
    const float* __restrict__ x, const float* __restrict__ hs,
    const float* __restrict__ Wir, const float* __restrict__ Whr,
    const float* __restrict__ Wiz, const float* __restrict__ Whz,
    const float* __restrict__ Win, const float* __restrict__ Whn) {
    __shared__ float stg[32][65];
    const int bx = blockIdx.x;
    if (bx < 2048) {
        const int mt = bx >> 3, sg = bx & 7;
        #pragma unroll
        for (int it = 0; it < 16; ++it) {
            int id = it * 256 + threadIdx.x;   // [0,4096)
            int j = id >> 9;                   // step within group
            int item = id & 511;
            int mtile = item >> 7;
            int lane_i = (item >> 2) & 31;
            int word = item & 3;
            int row = mtile * 16 + (lane_i >> 2) + (word & 1) * 8;
            int k = (lane_i & 3) * 2 + (word >> 1) * 8;
            int s = sg * 8 + j;
            const float* S = (s < 32) ? x : hs;
            int kglob = (s & 31) * 16 + k;
            float2 v = *reinterpret_cast<const float2*>(
                S + (size_t)(mt * 64 + row) * 512 + kglob);
            uint32_t lo, hi = pack_hi(v.x, v.y, lo);
            unsigned char* dst = g_Afrag + ((size_t)(mt * 64 + s)) * 4096
                               + (size_t)mtile * 1024 + (size_t)lane_i * 16
                               + (size_t)word * 4;
            *reinterpret_cast<uint32_t*>(dst)       = hi;   // plane 0 (hi)
            *reinterpret_cast<uint32_t*>(dst + 512) = lo;   // plane 1 (lo)
        }
    } else {
        const int w = bx - 2048;
        const int c = w & 31;
        const int ntg = w >> 5;                // 0..23 = nt*3 + g
        const int nt = ntg / 3, g = ntg % 3;
        const float* W = (c < 16)
            ? ((g == 0) ? Wir : (g == 1) ? Wiz : Win)
            : ((g == 0) ? Whr : (g == 1) ? Whz : Whn);
        const int k0 = (c & 15) * 32, n0 = nt * 64;
        #pragma unroll
        for (int it = 0; it < 8; ++it) {       // 2048 floats: 32k x 64n
            int id = it * 256 + threadIdx.x;
            int k = id >> 6, n = id & 63;
            stg[k][n] = W[(size_t)(k0 + k) * 512 + n0 + n];
        }
        __syncthreads();
        // write: [plane 2][h 2][n 64][32B]; pair p at byte (p&3)*8 + (p>>2)*4
        unsigned char* base = g_Wpack + (size_t)(ntg * 32 + c) * 8192;
        #pragma unroll
        for (int it = 0; it < 4; ++it) {       // 1024 pairs: 64n x 16kp
            int id = it * 256 + threadIdx.x;
            int n = id >> 4, kp = id & 15;
            int h = kp >> 3, pl = kp & 7;
            int off = h * 2048 + n * 32 + (pl & 3) * 8 + (pl >> 2) * 4;
            uint32_t lo, hi = pack_hi(stg[2 * kp][n], stg[2 * kp + 1][n], lo);
            *reinterpret_cast<uint32_t*>(base + off) = hi;
            *reinterpret_cast<uint32_t*>(base + 4096 + off) = lo;
        }
    }
}

// ---------------------------------------------------------------------------
// Load 6 B fragments (3 gates x hi/lo) for global k16-step g (clamped).
__device__ __forceinline__ void ldB(uint2 B[6], const unsigned char* bp, int g) {
    int c = g >> 1; if (c > 31) c = 31;
    const unsigned char* p = bp + (size_t)c * 8192 + (size_t)(g & 1) * 2048;
    B[0] = __ldg(reinterpret_cast<const uint2*>(p));
    B[1] = __ldg(reinterpret_cast<const uint2*>(p + 4096));
    B[2] = __ldg(reinterpret_cast<const uint2*>(p + 262144));
    B[3] = __ldg(reinterpret_cast<const uint2*>(p + 262144 + 4096));
    B[4] = __ldg(reinterpret_cast<const uint2*>(p + 524288));
    B[5] = __ldg(reinterpret_cast<const uint2*>(p + 524288 + 4096));
}

// One m32-half: 4 LDG.128 (A frags direct from L1) + 18 mma
// (gate-interleaved, acc reuse distance 6). Layout per step-block:
//   [mtile 4][plane 2][512B]; half h uses mtiles 2h, 2h+1.
__device__ __forceinline__ void half_mma_g(
    const unsigned char* p, const uint2 B[6],
    float aR0[4], float aR1[4], float aZ0[4], float aZ1[4],
    float aN0[4], float aN1[4]) {
    uint4 vh0 = __ldg(reinterpret_cast<const uint4*>(p));
    uint4 vl0 = __ldg(reinterpret_cast<const uint4*>(p + 512));
    uint4 vh1 = __ldg(reinterpret_cast<const uint4*>(p + 1024));
    uint4 vl1 = __ldg(reinterpret_cast<const uint4*>(p + 1536));
    const uint32_t* Ah0 = reinterpret_cast<const uint32_t*>(&vh0);
    const uint32_t* Al0 = reinterpret_cast<const uint32_t*>(&vl0);
    const uint32_t* Ah1 = reinterpret_cast<const uint32_t*>(&vh1);
    const uint32_t* Al1 = reinterpret_cast<const uint32_t*>(&vl1);
    // term 1: Ah x Bh
    mma16(aR0, Ah0, B[0].x, B[0].y);  mma16(aR1, Ah1, B[0].x, B[0].y);
    mma16(aZ0, Ah0, B[2].x, B[2].y);  mma16(aZ1, Ah1, B[2].x, B[2].y);
    mma16(aN0, Ah0, B[4].x, B[4].y);  mma16(aN1, Ah1, B[4].x, B[4].y);
    // term 2: Al x Bh
    mma16(aR0, Al0, B[0].x, B[0].y);  mma16(aR1, Al1, B[0].x, B[0].y);
    mma16(aZ0, Al0, B[2].x, B[2].y);  mma16(aZ1, Al1, B[2].x, B[2].y);
    mma16(aN0, Al0, B[4].x, B[4].y);  mma16(aN1, Al1, B[4].x, B[4].y);
    // term 3: Ah x Bl
    mma16(aR0, Ah0, B[1].x, B[1].y);  mma16(aR1, Ah1, B[1].x, B[1].y);
    mma16(aZ0, Ah0, B[3].x, B[3].y);  mma16(aZ1, Ah1, B[3].x, B[3].y);
    mma16(aN0, Ah0, B[5].x, B[5].y);  mma16(aN1, Ah1, B[5].x, B[5].y);
}

#define STEPG(S, CUR, NXT, AN)                                            \
    do {                                                                  \
        ldB(NXT, bp, (S) + 1);                                            \
        const unsigned char* sp = ap + (size_t)(S) * 4096;                \
        half_mma_g(sp,        CUR, aR[0], aR[1], aZ[0], aZ[1], AN[0], AN[1]); \
        half_mma_g(sp + 2048, CUR, aR[2], aR[3], aZ[2], aZ[3], AN[2], AN[3]); \
    } while (0)

__global__ void __launch_bounds__(256, 2) gru_main(
    const float* __restrict__ hs,
    const float* __restrict__ br, const float* __restrict__ bz,
    const float* __restrict__ bn, float* __restrict__ out) {
    const int tid = threadIdx.x;
    const int wid = tid >> 5, lane = tid & 31;
    const int wn = wid * 8;               // 0..56
    const int nt = blockIdx.x;            // 0..7
    const int mt = blockIdx.y;            // 0..255

    const unsigned char* ap = g_Afrag + (size_t)mt * 64 * 4096
                            + (size_t)lane * 16;
    const unsigned char* bp = g_Wpack + (size_t)nt * 786432
        + (size_t)(wn + (lane >> 2)) * 32 + (size_t)(lane & 3) * 8;

    float aR[4][4] = {}, aZ[4][4] = {}, aNi[4][4] = {}, aNh[4][4] = {};
    uint2 B0[6], B1[6];
    ldB(B0, bp, 0);

    for (int s = 0; s < 32; s += 2) {       // x phase -> n_i
        STEPG(s,     B0, B1, aNi);
        STEPG(s + 1, B1, B0, aNi);
    }
    for (int s = 32; s < 64; s += 2) {      // h phase -> n_h
        STEPG(s,     B0, B1, aNh);
        STEPG(s + 1, B1, B0, aNh);
    }

    // ---- epilogue ----
    #pragma unroll
    for (int mtile = 0; mtile < 4; ++mtile)
    #pragma unroll
    for (int i = 0; i < 4; ++i) {
        int rr = mt * 64 + mtile * 16 + (lane >> 2) + ((i >> 1) << 3);
        int cc = nt * 64 + wn + 2 * (lane & 3) + (i & 1);
        float pr = aR[mtile][i] + __ldg(br + cc);
        float pz = aZ[mtile][i] + __ldg(bz + cc);
        float rg = 1.0f / (1.0f + __expf(-pr));
        float zg = 1.0f / (1.0f + __expf(-pz));
        float ng = tanhf(aNi[mtile][i] + rg * aNh[mtile][i] + __ldg(bn + cc));
        float hv = hs[(size_t)rr * 512 + cc];
        out[(size_t)rr * 512 + cc] = (1.0f - zg) * ng + zg * hv;
    }
}

// ---------------------------------------------------------------------------
extern "C" void kernel_launch(void* const* d_in, const int* in_sizes, int n_in,
                              void* d_out, int out_size) {
    (void)in_sizes; (void)n_in; (void)out_size;
    const float* x   = (const float*)d_in[0];
    const float* h   = (const float*)d_in[1];
    const float* Wir = (const float*)d_in[2];
    const float* Whr = (const float*)d_in[3];
    const float* br  = (const float*)d_in[4];
    const float* Wiz = (const float*)d_in[5];
    const float* Whz = (const float*)d_in[6];
    const float* bz  = (const float*)d_in[7];
    const float* Win = (const float*)d_in[8];
    const float* Whn = (const float*)d_in[9];
    const float* bn  = (const float*)d_in[10];

    pack_all<<<2816, 256>>>(x, h, Wir, Whr, Wiz, Whz, Win, Whn);
    gru_main<<<dim3(NT_COUNT, MT_COUNT), 256>>>(
        h, br, bz, bn, (float*)d_out);
}